// round 2
// baseline (speedup 1.0000x reference)
#include <cuda_runtime.h>

#define NN   50000
#define EE   800000
#define TOTE (EE + NN)
#define INC  128
#define HID  96
#define OUTC 40
#define SLOPE 0.2f

// ---------------- scratch (device globals; no allocation allowed) ----------
__device__ float g_h1[(size_t)NN * HID];
__device__ float g_h2[(size_t)NN * OUTC];
__device__ float g_agg1[(size_t)NN * HID];
__device__ float g_agg2[(size_t)NN * OUTC];
__device__ float g_as[NN];
__device__ float g_ad[NN];
__device__ float g_m[NN];
__device__ float g_s[NN];
__device__ float g_e[TOTE];

// ---------------- helpers ---------------------------------------------------
__device__ __forceinline__ void atomicMaxF(float* a, float v) {
    if (v >= 0.f) atomicMax((int*)a, __float_as_int(v));
    else          atomicMin((unsigned int*)a, __float_as_uint(v));
}

__device__ __forceinline__ void redAdd4(float* p, float4 v) {
    asm volatile("red.global.add.v4.f32 [%0], {%1, %2, %3, %4};"
                 :: "l"(p), "f"(v.x), "f"(v.y), "f"(v.z), "f"(v.w)
                 : "memory");
}

// ---------------- init: zero agg buffer, m=-inf, s=0 ------------------------
__global__ void k_init(float* __restrict__ agg, int nAgg) {
    int i = blockIdx.x * blockDim.x + threadIdx.x;
    int stride = gridDim.x * blockDim.x;
    for (int j = i; j < nAgg; j += stride) agg[j] = 0.f;
    for (int j = i; j < NN; j += stride) {
        g_m[j] = __int_as_float(0xff800000);  // -inf
        g_s[j] = 0.f;
    }
}

// ---------------- GEMM: H[n,CO] = X[n,K] @ W[K,CO] --------------------------
template <int K, int CO>
__global__ void k_gemm(const float* __restrict__ X, const float* __restrict__ W,
                       float* __restrict__ H, int n) {
    __shared__ float Ws[K * CO];
    for (int i = threadIdx.x; i < K * CO; i += blockDim.x) Ws[i] = W[i];
    __syncthreads();
    const int CH = CO / 4;
    int total = n * CH;
    int idx = blockIdx.x * blockDim.x + threadIdx.x;
    int stride = gridDim.x * blockDim.x;
    for (; idx < total; idx += stride) {
        int row = idx / CH;
        int c = (idx % CH) * 4;
        const float* xr = X + (size_t)row * K;
        float4 acc = make_float4(0.f, 0.f, 0.f, 0.f);
#pragma unroll 4
        for (int k = 0; k < K; k++) {
            float xv = __ldg(xr + k);
            float4 w = *(const float4*)(Ws + k * CO + c);
            acc.x += xv * w.x; acc.y += xv * w.y;
            acc.z += xv * w.z; acc.w += xv * w.w;
        }
        *(float4*)(H + (size_t)row * CO + c) = acc;
    }
}

// ---------------- per-node attention scalars: as = h.a_src, ad = h.a_dst ----
template <int C>
__global__ void k_alphas(const float* __restrict__ h,
                         const float* __restrict__ asrc,
                         const float* __restrict__ adst) {
    int gw = (blockIdx.x * blockDim.x + threadIdx.x) >> 5;
    int lane = threadIdx.x & 31;
    if (gw >= NN) return;
    const float* row = h + (size_t)gw * C;
    float s1 = 0.f, s2 = 0.f;
#pragma unroll
    for (int i = 0; i < (C + 31) / 32; i++) {
        int c = lane + 32 * i;
        if (c < C) {
            float v = row[c];
            s1 += v * asrc[c];
            s2 += v * adst[c];
        }
    }
#pragma unroll
    for (int o = 16; o; o >>= 1) {
        s1 += __shfl_xor_sync(0xffffffffu, s1, o);
        s2 += __shfl_xor_sync(0xffffffffu, s2, o);
    }
    if (lane == 0) { g_as[gw] = s1; g_ad[gw] = s2; }
}

// ---------------- edge pass 1: raw attention + segment max ------------------
__global__ void k_edge_max(const int* __restrict__ ei) {
    int i = blockIdx.x * blockDim.x + threadIdx.x;
    if (i >= TOTE) return;
    int s, d;
    if (i < EE) { s = ei[i]; d = ei[EE + i]; }
    else        { s = d = i - EE; }
    float v = g_as[s] + g_ad[d];
    v = (v > 0.f) ? v : SLOPE * v;
    g_e[i] = v;
    atomicMaxF(&g_m[d], v);
}

// ---------------- edge pass 2: exp + segment sum -----------------------------
__global__ void k_edge_sum(const int* __restrict__ ei) {
    int i = blockIdx.x * blockDim.x + threadIdx.x;
    if (i >= TOTE) return;
    int d = (i < EE) ? ei[EE + i] : i - EE;
    float w = __expf(g_e[i] - g_m[d]);
    g_e[i] = w;
    atomicAdd(&g_s[d], w);
}

// ---------------- edge pass 3: weighted scatter-add aggregation -------------
// (normalization alpha = w / s[dst] folded in)
template <int C>
__global__ void k_edge_agg(const int* __restrict__ ei,
                           const float* __restrict__ h,
                           float* __restrict__ agg) {
    const int CH = C / 4;
    long long total = (long long)TOTE * CH;
    long long i = (long long)blockIdx.x * blockDim.x + threadIdx.x;
    if (i >= total) return;
    int e = (int)(i / CH);
    int c = (int)(i % CH) * 4;
    int s, d;
    if (e < EE) { s = ei[e]; d = ei[EE + e]; }
    else        { s = d = e - EE; }
    float a = g_e[e] / g_s[d];
    float4 hv = *(const float4*)(h + (size_t)s * C + c);
    float4 r = make_float4(a * hv.x, a * hv.y, a * hv.z, a * hv.w);
    redAdd4(agg + (size_t)d * C + c, r);
}

// ---------------- bias + relu (layer 1 epilogue), writes back into h --------
__global__ void k_bias_relu(float* __restrict__ h, const float* __restrict__ agg,
                            const float* __restrict__ b) {
    int i = blockIdx.x * blockDim.x + threadIdx.x;
    if (i >= NN * HID) return;
    int c = i % HID;
    float v = agg[i] + b[c];
    h[i] = (v > 0.f) ? v : 0.f;
}

// ---------------- bias + log_softmax (final output), one warp per node ------
__global__ void k_out(const float* __restrict__ agg, const float* __restrict__ b,
                      float* __restrict__ out) {
    int gw = (blockIdx.x * blockDim.x + threadIdx.x) >> 5;
    int lane = threadIdx.x & 31;
    if (gw >= NN) return;
    const float* row = agg + (size_t)gw * OUTC;
    float z0 = row[lane] + b[lane];
    bool v1 = lane < (OUTC - 32);
    float z1 = v1 ? (row[32 + lane] + b[32 + lane]) : -3.4e38f;
    float mx = fmaxf(z0, z1);
#pragma unroll
    for (int o = 16; o; o >>= 1) mx = fmaxf(mx, __shfl_xor_sync(0xffffffffu, mx, o));
    float sm = __expf(z0 - mx) + (v1 ? __expf(z1 - mx) : 0.f);
#pragma unroll
    for (int o = 16; o; o >>= 1) sm += __shfl_xor_sync(0xffffffffu, sm, o);
    float lse = mx + __logf(sm);
    out[(size_t)gw * OUTC + lane] = z0 - lse;
    if (v1) out[(size_t)gw * OUTC + 32 + lane] = z1 - lse;
}

// ---------------- launch -----------------------------------------------------
static inline int cdiv(long long a, int b) { return (int)((a + b - 1) / b); }

extern "C" void kernel_launch(void* const* d_in, const int* in_sizes, int n_in,
                              void* d_out, int out_size) {
    const float* x    = (const float*)d_in[0];
    const int*   ei   = (const int*)d_in[1];   // int32: JAX x64 disabled downgrades int64
    // d_in[2] = new_edge_indexs — unused by the reference
    const float* W1   = (const float*)d_in[3];
    const float* asr1 = (const float*)d_in[4];
    const float* ads1 = (const float*)d_in[5];
    const float* b1   = (const float*)d_in[6];
    const float* W2   = (const float*)d_in[7];
    const float* asr2 = (const float*)d_in[8];
    const float* ads2 = (const float*)d_in[9];
    const float* b2   = (const float*)d_in[10];
    float* out = (float*)d_out;

    float *h1, *h2, *agg1, *agg2;
    cudaGetSymbolAddress((void**)&h1, g_h1);
    cudaGetSymbolAddress((void**)&h2, g_h2);
    cudaGetSymbolAddress((void**)&agg1, g_agg1);
    cudaGetSymbolAddress((void**)&agg2, g_agg2);

    const int T = 256;

    // ---- layer 1 ----
    k_init<<<cdiv((long long)NN * HID, T), T>>>(agg1, NN * HID);
    k_gemm<INC, HID><<<cdiv((long long)NN * (HID / 4), T), T>>>(x, W1, h1, NN);
    k_alphas<HID><<<cdiv((long long)NN * 32, T), T>>>(h1, asr1, ads1);
    k_edge_max<<<cdiv(TOTE, T), T>>>(ei);
    k_edge_sum<<<cdiv(TOTE, T), T>>>(ei);
    k_edge_agg<HID><<<cdiv((long long)TOTE * (HID / 4), T), T>>>(ei, h1, agg1);
    k_bias_relu<<<cdiv((long long)NN * HID, T), T>>>(h1, agg1, b1);

    // ---- layer 2 ----
    k_init<<<cdiv((long long)NN * OUTC, T), T>>>(agg2, NN * OUTC);
    k_gemm<HID, OUTC><<<cdiv((long long)NN * (OUTC / 4), T), T>>>(h1, W2, h2, NN);
    k_alphas<OUTC><<<cdiv((long long)NN * 32, T), T>>>(h2, asr2, ads2);
    k_edge_max<<<cdiv(TOTE, T), T>>>(ei);
    k_edge_sum<<<cdiv(TOTE, T), T>>>(ei);
    k_edge_agg<OUTC><<<cdiv((long long)TOTE * (OUTC / 4), T), T>>>(ei, h2, agg2);
    k_out<<<cdiv((long long)NN * 32, T), T>>>(agg2, b2, out);
}

// round 3
// speedup vs baseline: 1.5903x; 1.5903x over previous
#include <cuda_runtime.h>

#define NN   50000
#define EE   800000
#define TOTE (EE + NN)
#define INC  128
#define HID  96
#define OUTC 40
#define SLOPE 0.2f

// ---------------- scratch (device globals; no allocation allowed) ----------
__device__ float g_h1[(size_t)NN * HID];
__device__ float g_h2[(size_t)NN * OUTC];
__device__ float g_agg1[(size_t)NN * HID];
__device__ float g_agg2[(size_t)NN * OUTC];
__device__ float g_as[NN];
__device__ float g_ad[NN];
__device__ float g_s[NN];
__device__ float g_e[TOTE];

// ---------------- helpers ---------------------------------------------------
__device__ __forceinline__ void redAdd4(float* p, float4 v) {
    asm volatile("red.global.add.v4.f32 [%0], {%1, %2, %3, %4};"
                 :: "l"(p), "f"(v.x), "f"(v.y), "f"(v.z), "f"(v.w)
                 : "memory");
}

// ---------------- init: zero agg buffer, s=0 --------------------------------
__global__ void k_init(float* __restrict__ agg, int nAgg) {
    int i = blockIdx.x * blockDim.x + threadIdx.x;
    int stride = gridDim.x * blockDim.x;
    for (int j = i; j < nAgg; j += stride) agg[j] = 0.f;
    for (int j = i; j < NN; j += stride) g_s[j] = 0.f;
}

// ---------------- tiled GEMM: H[n,CO] = X[n,K] @ W[K,CO] --------------------
// Thread tile: RPT rows x 4 cols, k packed in float4. Optional fused
// relu(x + bias) on the X-tile load (for layer-2 input = relu(agg1 + b1)).
template <int K, int CO, int TM, int TCOLS, int TROWS, bool FUSE>
__global__ void k_gemm_t(const float* __restrict__ X, const float* __restrict__ W,
                         const float* __restrict__ bias, float* __restrict__ H,
                         int n) {
    constexpr int KT = 32;
    constexpr int THREADS = TCOLS * TROWS;
    constexpr int RPT = TM / TROWS;
    __shared__ float Xs[TM][KT];
    __shared__ float Ws[KT][CO];

    const int tid  = threadIdx.x;
    const int tcol = tid % TCOLS;
    const int trow = tid / TCOLS;
    const int row0 = blockIdx.x * TM;

    float4 acc[RPT];
#pragma unroll
    for (int i = 0; i < RPT; i++) acc[i] = make_float4(0.f, 0.f, 0.f, 0.f);

    for (int kt = 0; kt < K; kt += KT) {
        // ---- load X tile (TM x KT), coalesced float4 ----
        for (int idx = tid; idx < TM * (KT / 4); idx += THREADS) {
            int r  = idx / (KT / 4);
            int c4 = idx % (KT / 4);
            int grow = row0 + r;
            float4 v = make_float4(0.f, 0.f, 0.f, 0.f);
            if (grow < n) {
                v = *(const float4*)(X + (size_t)grow * K + kt + c4 * 4);
                if constexpr (FUSE) {
                    const float* bb = bias + kt + c4 * 4;
                    v.x = fmaxf(v.x + bb[0], 0.f);
                    v.y = fmaxf(v.y + bb[1], 0.f);
                    v.z = fmaxf(v.z + bb[2], 0.f);
                    v.w = fmaxf(v.w + bb[3], 0.f);
                }
            }
            *(float4*)&Xs[r][c4 * 4] = v;
        }
        // ---- load W tile (KT x CO) ----
        for (int idx = tid; idx < KT * (CO / 4); idx += THREADS) {
            int r  = idx / (CO / 4);
            int c4 = idx % (CO / 4);
            *(float4*)&Ws[r][c4 * 4] =
                *(const float4*)(W + (size_t)(kt + r) * CO + c4 * 4);
        }
        __syncthreads();

        // ---- compute ----
#pragma unroll
        for (int k4 = 0; k4 < KT; k4 += 4) {
            float4 xs[RPT];
#pragma unroll
            for (int i = 0; i < RPT; i++)
                xs[i] = *(float4*)&Xs[trow * RPT + i][k4];
#pragma unroll
            for (int kk = 0; kk < 4; kk++) {
                float4 w = *(float4*)&Ws[k4 + kk][tcol * 4];
#pragma unroll
                for (int i = 0; i < RPT; i++) {
                    float xv = (kk == 0) ? xs[i].x : (kk == 1) ? xs[i].y
                             : (kk == 2) ? xs[i].z : xs[i].w;
                    acc[i].x += xv * w.x; acc[i].y += xv * w.y;
                    acc[i].z += xv * w.z; acc[i].w += xv * w.w;
                }
            }
        }
        __syncthreads();
    }

#pragma unroll
    for (int i = 0; i < RPT; i++) {
        int grow = row0 + trow * RPT + i;
        if (grow < n)
            *(float4*)(H + (size_t)grow * CO + tcol * 4) = acc[i];
    }
}

// ---------------- per-node attention scalars: as = h.a_src, ad = h.a_dst ----
template <int C>
__global__ void k_alphas(const float* __restrict__ h,
                         const float* __restrict__ asrc,
                         const float* __restrict__ adst) {
    int gw = (blockIdx.x * blockDim.x + threadIdx.x) >> 5;
    int lane = threadIdx.x & 31;
    if (gw >= NN) return;
    const float* row = h + (size_t)gw * C;
    float s1 = 0.f, s2 = 0.f;
#pragma unroll
    for (int i = 0; i < (C + 31) / 32; i++) {
        int c = lane + 32 * i;
        if (c < C) {
            float v = row[c];
            s1 += v * asrc[c];
            s2 += v * adst[c];
        }
    }
#pragma unroll
    for (int o = 16; o; o >>= 1) {
        s1 += __shfl_xor_sync(0xffffffffu, s1, o);
        s2 += __shfl_xor_sync(0xffffffffu, s2, o);
    }
    if (lane == 0) { g_as[gw] = s1; g_ad[gw] = s2; }
}

// ---------------- fused edge pass: w = exp(leaky(as+ad)); segment sum -------
// (max-shift dropped: softmax is shift-invariant and logits are O(10))
__global__ void k_edge_w(const int* __restrict__ ei) {
    int i = blockIdx.x * blockDim.x + threadIdx.x;
    if (i >= TOTE) return;
    int s, d;
    if (i < EE) { s = ei[i]; d = ei[EE + i]; }
    else        { s = d = i - EE; }
    float v = g_as[s] + g_ad[d];
    v = (v > 0.f) ? v : SLOPE * v;
    float w = __expf(v);
    g_e[i] = w;
    atomicAdd(&g_s[d], w);
}

// ---------------- weighted scatter-add aggregation (norm folded in) ---------
template <int C>
__global__ void k_edge_agg(const int* __restrict__ ei,
                           const float* __restrict__ h,
                           float* __restrict__ agg) {
    const int CH = C / 4;
    long long total = (long long)TOTE * CH;
    long long i = (long long)blockIdx.x * blockDim.x + threadIdx.x;
    if (i >= total) return;
    int e = (int)(i / CH);
    int c = (int)(i % CH) * 4;
    int s, d;
    if (e < EE) { s = ei[e]; d = ei[EE + e]; }
    else        { s = d = e - EE; }
    float a = g_e[e] / g_s[d];
    float4 hv = *(const float4*)(h + (size_t)s * C + c);
    float4 r = make_float4(a * hv.x, a * hv.y, a * hv.z, a * hv.w);
    redAdd4(agg + (size_t)d * C + c, r);
}

// ---------------- bias + log_softmax (final output), one warp per node ------
__global__ void k_out(const float* __restrict__ agg, const float* __restrict__ b,
                      float* __restrict__ out) {
    int gw = (blockIdx.x * blockDim.x + threadIdx.x) >> 5;
    int lane = threadIdx.x & 31;
    if (gw >= NN) return;
    const float* row = agg + (size_t)gw * OUTC;
    float z0 = row[lane] + b[lane];
    bool v1 = lane < (OUTC - 32);
    float z1 = v1 ? (row[32 + lane] + b[32 + lane]) : -3.4e38f;
    float mx = fmaxf(z0, z1);
#pragma unroll
    for (int o = 16; o; o >>= 1) mx = fmaxf(mx, __shfl_xor_sync(0xffffffffu, mx, o));
    float sm = __expf(z0 - mx) + (v1 ? __expf(z1 - mx) : 0.f);
#pragma unroll
    for (int o = 16; o; o >>= 1) sm += __shfl_xor_sync(0xffffffffu, sm, o);
    float lse = mx + __logf(sm);
    out[(size_t)gw * OUTC + lane] = z0 - lse;
    if (v1) out[(size_t)gw * OUTC + 32 + lane] = z1 - lse;
}

// ---------------- launch -----------------------------------------------------
static inline int cdiv(long long a, int b) { return (int)((a + b - 1) / b); }

extern "C" void kernel_launch(void* const* d_in, const int* in_sizes, int n_in,
                              void* d_out, int out_size) {
    const float* x    = (const float*)d_in[0];
    const int*   ei   = (const int*)d_in[1];   // int32 (JAX x64 disabled)
    // d_in[2] = new_edge_indexs — unused by the reference
    const float* W1   = (const float*)d_in[3];
    const float* asr1 = (const float*)d_in[4];
    const float* ads1 = (const float*)d_in[5];
    const float* b1   = (const float*)d_in[6];
    const float* W2   = (const float*)d_in[7];
    const float* asr2 = (const float*)d_in[8];
    const float* ads2 = (const float*)d_in[9];
    const float* b2   = (const float*)d_in[10];
    float* out = (float*)d_out;

    float *h1, *h2, *agg1, *agg2;
    cudaGetSymbolAddress((void**)&h1, g_h1);
    cudaGetSymbolAddress((void**)&h2, g_h2);
    cudaGetSymbolAddress((void**)&agg1, g_agg1);
    cudaGetSymbolAddress((void**)&agg2, g_agg2);

    const int T = 256;

    // ---- layer 1 ----
    k_init<<<cdiv((long long)NN * HID, T), T>>>(agg1, NN * HID);
    // GEMM1: K=128, CO=96, TM=64, 24x8=192 threads, 8 rows/thread
    k_gemm_t<INC, HID, 64, 24, 8, false>
        <<<cdiv(NN, 64), 24 * 8>>>(x, W1, nullptr, h1, NN);
    k_alphas<HID><<<cdiv((long long)NN * 32, T), T>>>(h1, asr1, ads1);
    k_edge_w<<<cdiv(TOTE, T), T>>>(ei);
    k_edge_agg<HID><<<cdiv((long long)TOTE * (HID / 4), T), T>>>(ei, h1, agg1);

    // ---- layer 2 ----
    k_init<<<cdiv((long long)NN * OUTC, T), T>>>(agg2, NN * OUTC);
    // GEMM2: K=96, CO=40, TM=128, 10x16=160 threads, 8 rows/thread,
    // fused relu(agg1 + b1) on input load
    k_gemm_t<HID, OUTC, 128, 10, 16, true>
        <<<cdiv(NN, 128), 10 * 16>>>(agg1, W2, b1, h2, NN);
    k_alphas<OUTC><<<cdiv((long long)NN * 32, T), T>>>(h2, asr2, ads2);
    k_edge_w<<<cdiv(TOTE, T), T>>>(ei);
    k_edge_agg<OUTC><<<cdiv((long long)TOTE * (OUTC / 4), T), T>>>(ei, h2, agg2);
    k_out<<<cdiv((long long)NN * 32, T), T>>>(agg2, b2, out);
}

// round 4
// speedup vs baseline: 1.6212x; 1.0194x over previous
#include <cuda_runtime.h>

#define NN   50000
#define EE   800000
#define TOTE (EE + NN)
#define INC  128
#define HID  96
#define OUTC 40
#define SLOPE 0.2f

// ---------------- scratch (device globals; no allocation allowed) ----------
__device__ float g_h1[(size_t)NN * HID];
__device__ float g_h2[(size_t)NN * OUTC];
__device__ float g_agg1[(size_t)NN * HID];
__device__ float g_agg2[(size_t)NN * OUTC];
__device__ float g_as[NN];
__device__ float g_ad[NN];
__device__ float g_s1[NN];
__device__ float g_s2[NN];

// ---------------- helpers ---------------------------------------------------
__device__ __forceinline__ void redAdd4(float* p, float4 v) {
    asm volatile("red.global.add.v4.f32 [%0], {%1, %2, %3, %4};"
                 :: "l"(p), "f"(v.x), "f"(v.y), "f"(v.z), "f"(v.w)
                 : "memory");
}

// ---------------- init: zero agg buffer, s, as, ad ---------------------------
__global__ void k_init(float* __restrict__ agg, int nAgg, float* __restrict__ s) {
    int i = blockIdx.x * blockDim.x + threadIdx.x;
    int stride = gridDim.x * blockDim.x;
    for (int j = i; j < nAgg; j += stride) agg[j] = 0.f;
    for (int j = i; j < NN; j += stride) {
        s[j] = 0.f;
        g_as[j] = 0.f;
        g_ad[j] = 0.f;
    }
}

// ---------------- tiled GEMM: H[n,CO] = X[n,K] @ W[K,CO] --------------------
// Epilogue fuses per-node attention scalars: as[row] += H_row . a_src etc.
// Optional fused relu(x/s + bias) on the X-tile load (layer-2 input).
template <int K, int CO, int TM, int TCOLS, int TROWS, bool FUSE>
__global__ void k_gemm_t(const float* __restrict__ X, const float* __restrict__ W,
                         const float* __restrict__ bias, const float* __restrict__ sdiv,
                         const float* __restrict__ asrc, const float* __restrict__ adst,
                         float* __restrict__ H, int n) {
    constexpr int KT = 32;
    constexpr int THREADS = TCOLS * TROWS;
    constexpr int RPT = TM / TROWS;
    __shared__ float Xs[TM][KT];
    __shared__ float Ws[KT][CO];

    const int tid  = threadIdx.x;
    const int tcol = tid % TCOLS;
    const int trow = tid / TCOLS;
    const int row0 = blockIdx.x * TM;

    float4 acc[RPT];
#pragma unroll
    for (int i = 0; i < RPT; i++) acc[i] = make_float4(0.f, 0.f, 0.f, 0.f);

    for (int kt = 0; kt < K; kt += KT) {
        // ---- load X tile (TM x KT), coalesced float4 ----
        for (int idx = tid; idx < TM * (KT / 4); idx += THREADS) {
            int r  = idx / (KT / 4);
            int c4 = idx % (KT / 4);
            int grow = row0 + r;
            float4 v = make_float4(0.f, 0.f, 0.f, 0.f);
            if (grow < n) {
                v = *(const float4*)(X + (size_t)grow * K + kt + c4 * 4);
                if constexpr (FUSE) {
                    float inv = 1.f / sdiv[grow];
                    const float* bb = bias + kt + c4 * 4;
                    v.x = fmaxf(v.x * inv + bb[0], 0.f);
                    v.y = fmaxf(v.y * inv + bb[1], 0.f);
                    v.z = fmaxf(v.z * inv + bb[2], 0.f);
                    v.w = fmaxf(v.w * inv + bb[3], 0.f);
                }
            }
            *(float4*)&Xs[r][c4 * 4] = v;
        }
        // ---- load W tile (KT x CO) ----
        for (int idx = tid; idx < KT * (CO / 4); idx += THREADS) {
            int r  = idx / (CO / 4);
            int c4 = idx % (CO / 4);
            *(float4*)&Ws[r][c4 * 4] =
                *(const float4*)(W + (size_t)(kt + r) * CO + c4 * 4);
        }
        __syncthreads();

        // ---- compute ----
#pragma unroll
        for (int k4 = 0; k4 < KT; k4 += 4) {
            float4 xs[RPT];
#pragma unroll
            for (int i = 0; i < RPT; i++)
                xs[i] = *(float4*)&Xs[trow * RPT + i][k4];
#pragma unroll
            for (int kk = 0; kk < 4; kk++) {
                float4 w = *(float4*)&Ws[k4 + kk][tcol * 4];
#pragma unroll
                for (int i = 0; i < RPT; i++) {
                    float xv = (kk == 0) ? xs[i].x : (kk == 1) ? xs[i].y
                             : (kk == 2) ? xs[i].z : xs[i].w;
                    acc[i].x += xv * w.x; acc[i].y += xv * w.y;
                    acc[i].z += xv * w.z; acc[i].w += xv * w.w;
                }
            }
        }
        __syncthreads();
    }

    // ---- epilogue: store H and accumulate attention scalars ----
    float4 vs = *(const float4*)(asrc + tcol * 4);
    float4 vd = *(const float4*)(adst + tcol * 4);
#pragma unroll
    for (int i = 0; i < RPT; i++) {
        int grow = row0 + trow * RPT + i;
        if (grow < n) {
            *(float4*)(H + (size_t)grow * CO + tcol * 4) = acc[i];
            float ps = acc[i].x * vs.x + acc[i].y * vs.y + acc[i].z * vs.z + acc[i].w * vs.w;
            float pd = acc[i].x * vd.x + acc[i].y * vd.y + acc[i].z * vd.z + acc[i].w * vd.w;
            atomicAdd(&g_as[grow], ps);
            atomicAdd(&g_ad[grow], pd);
        }
    }
}

// ---------------- fused edge pass: w=exp(leaky(as+ad)); scatter w*h; sum w ---
template <int C>
__global__ void k_edge_agg(const int* __restrict__ ei,
                           const float* __restrict__ h,
                           float* __restrict__ agg,
                           float* __restrict__ svec) {
    const int CH = C / 4;
    long long total = (long long)TOTE * CH;
    long long i = (long long)blockIdx.x * blockDim.x + threadIdx.x;
    if (i >= total) return;
    int e = (int)(i / CH);
    int c = (int)(i % CH) * 4;
    int s, d;
    if (e < EE) { s = ei[e]; d = ei[EE + e]; }
    else        { s = d = e - EE; }
    float v = g_as[s] + g_ad[d];
    v = (v > 0.f) ? v : SLOPE * v;
    float w = __expf(v);
    float4 hv = *(const float4*)(h + (size_t)s * C + c);
    float4 r = make_float4(w * hv.x, w * hv.y, w * hv.z, w * hv.w);
    redAdd4(agg + (size_t)d * C + c, r);
    if (c == 0) atomicAdd(&svec[d], w);
}

// ---------------- bias + norm + log_softmax (final), one warp per node ------
__global__ void k_out(const float* __restrict__ agg, const float* __restrict__ b,
                      const float* __restrict__ svec, float* __restrict__ out) {
    int gw = (blockIdx.x * blockDim.x + threadIdx.x) >> 5;
    int lane = threadIdx.x & 31;
    if (gw >= NN) return;
    const float* row = agg + (size_t)gw * OUTC;
    float inv = 1.f / svec[gw];
    float z0 = row[lane] * inv + b[lane];
    bool v1 = lane < (OUTC - 32);
    float z1 = v1 ? (row[32 + lane] * inv + b[32 + lane]) : -3.4e38f;
    float mx = fmaxf(z0, z1);
#pragma unroll
    for (int o = 16; o; o >>= 1) mx = fmaxf(mx, __shfl_xor_sync(0xffffffffu, mx, o));
    float sm = __expf(z0 - mx) + (v1 ? __expf(z1 - mx) : 0.f);
#pragma unroll
    for (int o = 16; o; o >>= 1) sm += __shfl_xor_sync(0xffffffffu, sm, o);
    float lse = mx + __logf(sm);
    out[(size_t)gw * OUTC + lane] = z0 - lse;
    if (v1) out[(size_t)gw * OUTC + 32 + lane] = z1 - lse;
}

// ---------------- launch -----------------------------------------------------
static inline int cdiv(long long a, int b) { return (int)((a + b - 1) / b); }

extern "C" void kernel_launch(void* const* d_in, const int* in_sizes, int n_in,
                              void* d_out, int out_size) {
    const float* x    = (const float*)d_in[0];
    const int*   ei   = (const int*)d_in[1];   // int32 (JAX x64 disabled)
    // d_in[2] = new_edge_indexs — unused by the reference
    const float* W1   = (const float*)d_in[3];
    const float* asr1 = (const float*)d_in[4];
    const float* ads1 = (const float*)d_in[5];
    const float* b1   = (const float*)d_in[6];
    const float* W2   = (const float*)d_in[7];
    const float* asr2 = (const float*)d_in[8];
    const float* ads2 = (const float*)d_in[9];
    const float* b2   = (const float*)d_in[10];
    float* out = (float*)d_out;

    float *h1, *h2, *agg1, *agg2, *s1, *s2;
    cudaGetSymbolAddress((void**)&h1, g_h1);
    cudaGetSymbolAddress((void**)&h2, g_h2);
    cudaGetSymbolAddress((void**)&agg1, g_agg1);
    cudaGetSymbolAddress((void**)&agg2, g_agg2);
    cudaGetSymbolAddress((void**)&s1, g_s1);
    cudaGetSymbolAddress((void**)&s2, g_s2);

    const int T = 256;

    // ---- layer 1 ----
    k_init<<<cdiv((long long)NN * HID, T), T>>>(agg1, NN * HID, s1);
    k_gemm_t<INC, HID, 64, 24, 8, false>
        <<<cdiv(NN, 64), 24 * 8>>>(x, W1, nullptr, nullptr, asr1, ads1, h1, NN);
    k_edge_agg<HID><<<cdiv((long long)TOTE * (HID / 4), T), T>>>(ei, h1, agg1, s1);

    // ---- layer 2 ----
    k_init<<<cdiv((long long)NN * OUTC, T), T>>>(agg2, NN * OUTC, s2);
    // X-load fuses relu(agg1/s1 + b1); epilogue fuses layer-2 alphas
    k_gemm_t<HID, OUTC, 128, 10, 16, true>
        <<<cdiv(NN, 128), 10 * 16>>>(agg1, W2, b1, s1, asr2, ads2, h2, NN);
    k_edge_agg<OUTC><<<cdiv((long long)TOTE * (OUTC / 4), T), T>>>(ei, h2, agg2, s2);
    k_out<<<cdiv((long long)NN * 32, T), T>>>(agg2, b2, s2, out);
}

// round 5
// speedup vs baseline: 2.0328x; 1.2539x over previous
#include <cuda_runtime.h>

#define NN   50000
#define EE   800000
#define INC  128
#define HID  96
#define OUTC 40
#define SLOPE 0.2f

#define SCAN_B 1024
#define SCAN_NB ((NN + SCAN_B - 1) / SCAN_B)

// ---------------- scratch (device globals; no allocation allowed) ----------
__device__ float g_h1[(size_t)NN * HID];
__device__ float g_h2[(size_t)NN * OUTC];
__device__ float g_agg1[(size_t)NN * HID];   // normalized layer-1 aggregation
__device__ float g_agg2[(size_t)NN * OUTC];  // normalized layer-2 aggregation
__device__ float g_as1[NN], g_ad1[NN];
__device__ float g_as2[NN], g_ad2[NN];
__device__ int   g_cnt[NN];
__device__ int   g_off[NN + 1];
__device__ int   g_cur[NN];
__device__ int   g_part[SCAN_NB];
__device__ int   g_csr[EE];

// ---------------- zero pass --------------------------------------------------
__global__ void k_zero() {
    int i = blockIdx.x * blockDim.x + threadIdx.x;
    if (i < NN) {
        g_cnt[i] = 0;
        g_as1[i] = 0.f; g_ad1[i] = 0.f;
        g_as2[i] = 0.f; g_ad2[i] = 0.f;
    }
}

// ---------------- CSR build --------------------------------------------------
__global__ void k_hist(const int* __restrict__ ei) {
    int i = blockIdx.x * blockDim.x + threadIdx.x;
    if (i < EE) atomicAdd(&g_cnt[ei[EE + i]], 1);
}

__global__ void k_scan1() {
    __shared__ int sm[SCAN_B];
    int tid = threadIdx.x;
    int g = blockIdx.x * SCAN_B + tid;
    int v = (g < NN) ? g_cnt[g] : 0;
    sm[tid] = v;
    __syncthreads();
#pragma unroll
    for (int ofs = 1; ofs < SCAN_B; ofs <<= 1) {
        int t = (tid >= ofs) ? sm[tid - ofs] : 0;
        __syncthreads();
        sm[tid] += t;
        __syncthreads();
    }
    if (g < NN) g_off[g] = sm[tid] - v;     // exclusive within block
    if (tid == SCAN_B - 1) g_part[blockIdx.x] = sm[tid];
}

__global__ void k_scan2() {
    __shared__ int sm[SCAN_NB];
    int tid = threadIdx.x;
    if (tid < SCAN_NB) sm[tid] = g_part[tid];
    __syncthreads();
    if (tid == 0) {
        int run = 0;
        for (int i = 0; i < SCAN_NB; i++) { int t = sm[i]; sm[i] = run; run += t; }
    }
    __syncthreads();
    if (tid < SCAN_NB) g_part[tid] = sm[tid];
}

__global__ void k_scan3() {
    int g = blockIdx.x * SCAN_B + threadIdx.x;
    if (g < NN) {
        int o = g_off[g] + g_part[blockIdx.x];
        g_off[g] = o;
        g_cur[g] = o;
    }
    if (g == 0) g_off[NN] = EE;
}

__global__ void k_fill(const int* __restrict__ ei) {
    int i = blockIdx.x * blockDim.x + threadIdx.x;
    if (i >= EE) return;
    int d = ei[EE + i];
    int pos = atomicAdd(&g_cur[d], 1);
    g_csr[pos] = ei[i];
}

// ---------------- tiled GEMM: H[n,CO] = X[n,K] @ W[K,CO] --------------------
// Epilogue fuses per-node attention scalars (atomicAdd partials).
// Optional fused relu(x + bias) on the X-tile load (layer-2 input).
template <int K, int CO, int TM, int TCOLS, int TROWS, bool FUSE>
__global__ void k_gemm_t(const float* __restrict__ X, const float* __restrict__ W,
                         const float* __restrict__ bias,
                         const float* __restrict__ asrc, const float* __restrict__ adst,
                         float* __restrict__ oas, float* __restrict__ oad,
                         float* __restrict__ H, int n) {
    constexpr int KT = 32;
    constexpr int THREADS = TCOLS * TROWS;
    constexpr int RPT = TM / TROWS;
    __shared__ float Xs[TM][KT];
    __shared__ float Ws[KT][CO];

    const int tid  = threadIdx.x;
    const int tcol = tid % TCOLS;
    const int trow = tid / TCOLS;
    const int row0 = blockIdx.x * TM;

    float4 acc[RPT];
#pragma unroll
    for (int i = 0; i < RPT; i++) acc[i] = make_float4(0.f, 0.f, 0.f, 0.f);

    for (int kt = 0; kt < K; kt += KT) {
        for (int idx = tid; idx < TM * (KT / 4); idx += THREADS) {
            int r  = idx / (KT / 4);
            int c4 = idx % (KT / 4);
            int grow = row0 + r;
            float4 v = make_float4(0.f, 0.f, 0.f, 0.f);
            if (grow < n) {
                v = *(const float4*)(X + (size_t)grow * K + kt + c4 * 4);
                if constexpr (FUSE) {
                    const float* bb = bias + kt + c4 * 4;
                    v.x = fmaxf(v.x + bb[0], 0.f);
                    v.y = fmaxf(v.y + bb[1], 0.f);
                    v.z = fmaxf(v.z + bb[2], 0.f);
                    v.w = fmaxf(v.w + bb[3], 0.f);
                }
            }
            *(float4*)&Xs[r][c4 * 4] = v;
        }
        for (int idx = tid; idx < KT * (CO / 4); idx += THREADS) {
            int r  = idx / (CO / 4);
            int c4 = idx % (CO / 4);
            *(float4*)&Ws[r][c4 * 4] =
                *(const float4*)(W + (size_t)(kt + r) * CO + c4 * 4);
        }
        __syncthreads();

#pragma unroll
        for (int k4 = 0; k4 < KT; k4 += 4) {
            float4 xs[RPT];
#pragma unroll
            for (int i = 0; i < RPT; i++)
                xs[i] = *(float4*)&Xs[trow * RPT + i][k4];
#pragma unroll
            for (int kk = 0; kk < 4; kk++) {
                float4 w = *(float4*)&Ws[k4 + kk][tcol * 4];
#pragma unroll
                for (int i = 0; i < RPT; i++) {
                    float xv = (kk == 0) ? xs[i].x : (kk == 1) ? xs[i].y
                             : (kk == 2) ? xs[i].z : xs[i].w;
                    acc[i].x += xv * w.x; acc[i].y += xv * w.y;
                    acc[i].z += xv * w.z; acc[i].w += xv * w.w;
                }
            }
        }
        __syncthreads();
    }

    float4 vs = *(const float4*)(asrc + tcol * 4);
    float4 vd = *(const float4*)(adst + tcol * 4);
#pragma unroll
    for (int i = 0; i < RPT; i++) {
        int grow = row0 + trow * RPT + i;
        if (grow < n) {
            *(float4*)(H + (size_t)grow * CO + tcol * 4) = acc[i];
            float ps = acc[i].x * vs.x + acc[i].y * vs.y + acc[i].z * vs.z + acc[i].w * vs.w;
            float pd = acc[i].x * vd.x + acc[i].y * vd.y + acc[i].z * vd.z + acc[i].w * vd.w;
            atomicAdd(&oas[grow], ps);
            atomicAdd(&oad[grow], pd);
        }
    }
}

// ---------------- CSR gather aggregation: one warp per dst node --------------
// out[node] = (w_self*h[node] + sum_e w_e*h[src_e]) / (w_self + sum_e w_e)
template <int C>
__global__ void k_agg_csr(const float* __restrict__ h,
                          const float* __restrict__ as,
                          const float* __restrict__ ad,
                          float* __restrict__ aggout) {
    constexpr int CPL = (C + 31) / 32;   // channels per lane
    int node = blockIdx.x * (blockDim.x >> 5) + (threadIdx.x >> 5);
    int lane = threadIdx.x & 31;
    if (node >= NN) return;

    float ad_n = ad[node];
    float as_n = as[node];
    float vself = as_n + ad_n;
    vself = (vself > 0.f) ? vself : SLOPE * vself;
    float wself = __expf(vself);

    float acc[CPL];
#pragma unroll
    for (int j = 0; j < CPL; j++) {
        int c = lane + 32 * j;
        acc[j] = (c < C) ? wself * h[(size_t)node * C + c] : 0.f;
    }

    int beg = g_off[node];
    int end = g_off[node + 1];
    float sloc = 0.f;

    for (int base = beg; base < end; base += 32) {
        int e = base + lane;
        bool valid = e < end;
        int src = valid ? g_csr[e] : 0;
        float w = 0.f;
        if (valid) {
            float v = as[src] + ad_n;
            v = (v > 0.f) ? v : SLOPE * v;
            w = __expf(v);
        }
        sloc += w;
        int cnt = min(32, end - base);
        for (int k = 0; k < cnt; k++) {
            float wk = __shfl_sync(0xffffffffu, w, k);
            int   sk = __shfl_sync(0xffffffffu, src, k);
            const float* hr = h + (size_t)sk * C;
#pragma unroll
            for (int j = 0; j < CPL; j++) {
                int c = lane + 32 * j;
                if (c < C) acc[j] += wk * hr[c];
            }
        }
    }

    // total weight
#pragma unroll
    for (int o = 16; o; o >>= 1) sloc += __shfl_xor_sync(0xffffffffu, sloc, o);
    float inv = 1.f / (sloc + wself);

#pragma unroll
    for (int j = 0; j < CPL; j++) {
        int c = lane + 32 * j;
        if (c < C) aggout[(size_t)node * C + c] = acc[j] * inv;
    }
}

// ---------------- bias + log_softmax (final output), one warp per node ------
__global__ void k_out(const float* __restrict__ agg, const float* __restrict__ b,
                      float* __restrict__ out) {
    int gw = (blockIdx.x * blockDim.x + threadIdx.x) >> 5;
    int lane = threadIdx.x & 31;
    if (gw >= NN) return;
    const float* row = agg + (size_t)gw * OUTC;
    float z0 = row[lane] + b[lane];
    bool v1 = lane < (OUTC - 32);
    float z1 = v1 ? (row[32 + lane] + b[32 + lane]) : -3.4e38f;
    float mx = fmaxf(z0, z1);
#pragma unroll
    for (int o = 16; o; o >>= 1) mx = fmaxf(mx, __shfl_xor_sync(0xffffffffu, mx, o));
    float sm = __expf(z0 - mx) + (v1 ? __expf(z1 - mx) : 0.f);
#pragma unroll
    for (int o = 16; o; o >>= 1) sm += __shfl_xor_sync(0xffffffffu, sm, o);
    float lse = mx + __logf(sm);
    out[(size_t)gw * OUTC + lane] = z0 - lse;
    if (v1) out[(size_t)gw * OUTC + 32 + lane] = z1 - lse;
}

// ---------------- launch -----------------------------------------------------
static inline int cdiv(long long a, int b) { return (int)((a + b - 1) / b); }

extern "C" void kernel_launch(void* const* d_in, const int* in_sizes, int n_in,
                              void* d_out, int out_size) {
    const float* x    = (const float*)d_in[0];
    const int*   ei   = (const int*)d_in[1];   // int32 (JAX x64 disabled)
    // d_in[2] = new_edge_indexs — unused by the reference
    const float* W1   = (const float*)d_in[3];
    const float* asr1 = (const float*)d_in[4];
    const float* ads1 = (const float*)d_in[5];
    const float* b1   = (const float*)d_in[6];
    const float* W2   = (const float*)d_in[7];
    const float* asr2 = (const float*)d_in[8];
    const float* ads2 = (const float*)d_in[9];
    const float* b2   = (const float*)d_in[10];
    float* out = (float*)d_out;

    float *h1, *h2, *agg1, *agg2, *as1, *ad1, *as2, *ad2;
    cudaGetSymbolAddress((void**)&h1, g_h1);
    cudaGetSymbolAddress((void**)&h2, g_h2);
    cudaGetSymbolAddress((void**)&agg1, g_agg1);
    cudaGetSymbolAddress((void**)&agg2, g_agg2);
    cudaGetSymbolAddress((void**)&as1, g_as1);
    cudaGetSymbolAddress((void**)&ad1, g_ad1);
    cudaGetSymbolAddress((void**)&as2, g_as2);
    cudaGetSymbolAddress((void**)&ad2, g_ad2);

    const int T = 256;

    // ---- CSR build (once, reused by both layers) ----
    k_zero<<<cdiv(NN, T), T>>>();
    k_hist<<<cdiv(EE, T), T>>>(ei);
    k_scan1<<<SCAN_NB, SCAN_B>>>();
    k_scan2<<<1, 64>>>();
    k_scan3<<<SCAN_NB, SCAN_B>>>();
    k_fill<<<cdiv(EE, T), T>>>(ei);

    // ---- layer 1 ----
    k_gemm_t<INC, HID, 64, 24, 8, false>
        <<<cdiv(NN, 64), 24 * 8>>>(x, W1, nullptr, asr1, ads1, as1, ad1, h1, NN);
    k_agg_csr<HID><<<cdiv(NN, 8), 256>>>(h1, as1, ad1, agg1);

    // ---- layer 2 ----
    k_gemm_t<HID, OUTC, 128, 10, 16, true>
        <<<cdiv(NN, 128), 10 * 16>>>(agg1, W2, b1, asr2, ads2, as2, ad2, h2, NN);
    k_agg_csr<OUTC><<<cdiv(NN, 8), 256>>>(h2, as2, ad2, agg2);
    k_out<<<cdiv((long long)NN * 32, T), T>>>(agg2, b2, out);
}